// round 1
// baseline (speedup 1.0000x reference)
#include <cuda_runtime.h>
#include <mma.h>
#include <type_traits>
#include <math.h>

using namespace nvcuda;

#define SEQ 2048
#define DMODEL 2048
#define NHEAD 16
#define EHEAD 128
#define NE3 384  // 3*E

// Scratch (static device allocations are allowed)
__device__ float g_qkv[(size_t)NHEAD * SEQ * NE3];          // ~50 MB, [h][s][3e]
__device__ float g_scores[(size_t)NHEAD * SEQ * SEQ];       // ~268 MB, [h][s][t]

// ---------------- 3xTF32 batched GEMM ----------------
// C[z] = alpha * A[z] * B[z]
// A: MxK row-major (lda). B: KxN. If B_COL, B is stored so that element (k,n)
// sits at B[n*ldb + k] (i.e. we multiply by B^T of a row-major [N][K] array).
constexpr int BM = 64, BN = 64, BK = 16;
constexpr int ASP   = BK + 4;   // As pitch (multiple of 4 for wmma ldm)
constexpr int BSP_R = BN + 4;   // Bs pitch, row-major [BK][BN]
constexpr int BSP_C = BK + 4;   // Bs pitch, col-major [BN][BK]

template <bool B_COL>
__global__ void gemm_tf32x3(const float* __restrict__ A,
                            const float* __restrict__ B,
                            float* __restrict__ C,
                            int M, int N, int K,
                            int lda, int ldb, int ldc,
                            long long aBatch, long long bBatch, long long cBatch,
                            float alpha)
{
    __shared__ float As[BM][ASP];
    __shared__ float Bs[BN * BSP_C];   // big enough for both layouts (1280 >= 1088)

    const float* Ab = A + (long long)blockIdx.z * aBatch;
    const float* Bb = B + (long long)blockIdx.z * bBatch;
    float*       Cb = C + (long long)blockIdx.z * cBatch;

    const int m0 = blockIdx.y * BM;
    const int n0 = blockIdx.x * BN;
    const int tid = threadIdx.x;          // 256 threads = 8 warps
    const int warpId = tid >> 5;
    const int wr = warpId >> 1;           // 0..3 -> 16-row band
    const int wc = warpId & 1;            // 0..1 -> 32-col band

    using BLayout = typename std::conditional<B_COL, wmma::col_major, wmma::row_major>::type;
    wmma::fragment<wmma::matrix_a, 16, 16, 8, wmma::precision::tf32, wmma::row_major> ah, al;
    wmma::fragment<wmma::matrix_b, 16, 16, 8, wmma::precision::tf32, BLayout> bh, bl;
    wmma::fragment<wmma::accumulator, 16, 16, 8, float> acc[2];
    wmma::fill_fragment(acc[0], 0.0f);
    wmma::fill_fragment(acc[1], 0.0f);

    for (int k0 = 0; k0 < K; k0 += BK) {
        // load A tile 64x16
        #pragma unroll
        for (int i = tid; i < BM * BK; i += 256) {
            int m = i >> 4, k = i & 15;
            As[m][k] = Ab[(size_t)(m0 + m) * lda + (k0 + k)];
        }
        // load B tile
        if (B_COL) {
            #pragma unroll
            for (int i = tid; i < BN * BK; i += 256) {
                int n = i >> 4, k = i & 15;
                Bs[n * BSP_C + k] = Bb[(size_t)(n0 + n) * ldb + (k0 + k)];
            }
        } else {
            #pragma unroll
            for (int i = tid; i < BK * BN; i += 256) {
                int k = i >> 6, n = i & 63;
                Bs[k * BSP_R + n] = Bb[(size_t)(k0 + k) * ldb + (n0 + n)];
            }
        }
        __syncthreads();

        #pragma unroll
        for (int k8 = 0; k8 < BK; k8 += 8) {
            // A fragment + split
            wmma::load_matrix_sync(ah, &As[wr * 16][k8], ASP);
            #pragma unroll
            for (int i = 0; i < ah.num_elements; i++) {
                float v = ah.x[i];
                float hi = wmma::__float_to_tf32(v);
                ah.x[i] = hi;
                al.x[i] = wmma::__float_to_tf32(v - hi);
            }
            #pragma unroll
            for (int j = 0; j < 2; j++) {
                const float* bptr;
                int bld;
                if (B_COL) { bptr = &Bs[(wc * 32 + j * 16) * BSP_C + k8]; bld = BSP_C; }
                else       { bptr = &Bs[k8 * BSP_R + (wc * 32 + j * 16)]; bld = BSP_R; }
                wmma::load_matrix_sync(bh, bptr, bld);
                #pragma unroll
                for (int i = 0; i < bh.num_elements; i++) {
                    float v = bh.x[i];
                    float hi = wmma::__float_to_tf32(v);
                    bh.x[i] = hi;
                    bl.x[i] = wmma::__float_to_tf32(v - hi);
                }
                // small terms first, then hi*hi
                wmma::mma_sync(acc[j], ah, bl, acc[j]);
                wmma::mma_sync(acc[j], al, bh, acc[j]);
                wmma::mma_sync(acc[j], ah, bh, acc[j]);
            }
        }
        __syncthreads();
    }

    #pragma unroll
    for (int j = 0; j < 2; j++) {
        #pragma unroll
        for (int i = 0; i < acc[j].num_elements; i++) acc[j].x[i] *= alpha;
        wmma::store_matrix_sync(&Cb[(size_t)(m0 + wr * 16) * ldc + (n0 + wc * 32 + j * 16)],
                                acc[j], ldc, wmma::mem_row_major);
    }
}

// ---------------- row softmax ----------------
__global__ void softmax_rows(float* __restrict__ sc)
{
    size_t row = blockIdx.x;
    float* p = sc + row * (size_t)SEQ;
    const int tid = threadIdx.x, lane = tid & 31, wid = tid >> 5;
    __shared__ float red[8];
    __shared__ float bval;

    float mx = -1e30f;
    for (int i = tid; i < SEQ; i += 256) mx = fmaxf(mx, p[i]);
    #pragma unroll
    for (int o = 16; o; o >>= 1) mx = fmaxf(mx, __shfl_xor_sync(0xffffffffu, mx, o));
    if (lane == 0) red[wid] = mx;
    __syncthreads();
    if (tid == 0) {
        float m = red[0];
        #pragma unroll
        for (int i = 1; i < 8; i++) m = fmaxf(m, red[i]);
        bval = m;
    }
    __syncthreads();
    mx = bval;

    float s = 0.0f;
    for (int i = tid; i < SEQ; i += 256) {
        float e = __expf(p[i] - mx);
        p[i] = e;
        s += e;
    }
    #pragma unroll
    for (int o = 16; o; o >>= 1) s += __shfl_xor_sync(0xffffffffu, s, o);
    if (lane == 0) red[wid] = s;
    __syncthreads();
    if (tid == 0) {
        float t = 0.0f;
        #pragma unroll
        for (int i = 0; i < 8; i++) t += red[i];
        bval = 1.0f / t;
    }
    __syncthreads();
    float inv = bval;
    for (int i = tid; i < SEQ; i += 256) p[i] *= inv;
}

extern "C" void kernel_launch(void* const* d_in, const int* in_sizes, int n_in,
                              void* d_out, int out_size)
{
    const float* x = (const float*)d_in[0];       // [S, D]
    const float* w = (const float*)d_in[1];       // [H, D, 3E]
    float* out = (float*)d_out;                   // [S, H*E]

    float *qkv, *scores;
    cudaGetSymbolAddress((void**)&qkv, g_qkv);
    cudaGetSymbolAddress((void**)&scores, g_scores);

    const float inv_sqrt_e = 0.08838834764831845f;  // 1/sqrt(128)

    // 1) qkv[h][s][3e] = x @ w[h]
    {
        dim3 grid(NE3 / BN, SEQ / BM, NHEAD);
        gemm_tf32x3<false><<<grid, 256>>>(x, w, qkv,
            SEQ, NE3, DMODEL,
            DMODEL, NE3, NE3,
            0LL, (long long)DMODEL * NE3, (long long)SEQ * NE3, 1.0f);
    }
    // 2) scores[h][s][t] = (Q @ K^T) / sqrt(E)
    {
        dim3 grid(SEQ / BN, SEQ / BM, NHEAD);
        gemm_tf32x3<true><<<grid, 256>>>(qkv /*Q at off 0*/, qkv + EHEAD /*K*/, scores,
            SEQ, SEQ, EHEAD,
            NE3, NE3, SEQ,
            (long long)SEQ * NE3, (long long)SEQ * NE3, (long long)SEQ * SEQ, inv_sqrt_e);
    }
    // 3) softmax rows
    softmax_rows<<<NHEAD * SEQ, 256>>>(scores);
    // 4) out[s, h*E + e] = attn @ V
    {
        dim3 grid(EHEAD / BN, SEQ / BM, NHEAD);
        gemm_tf32x3<false><<<grid, 256>>>(scores, qkv + 2 * EHEAD /*V*/, out,
            SEQ, EHEAD, SEQ,
            SEQ, NE3, DMODEL,
            (long long)SEQ * SEQ, (long long)SEQ * NE3, (long long)EHEAD, 1.0f);
    }
}

// round 5
// speedup vs baseline: 4.3267x; 4.3267x over previous
#include <cuda_runtime.h>
#include <cuda_bf16.h>
#include <cstdint>
#include <math.h>

#define SEQ 2048
#define DM 2048
#define H 16
#define E 128
#define NE3 384

// ----------------- scratch (static device allocations) -----------------
__device__ __nv_bfloat16 g_xh[(size_t)SEQ * DM];
__device__ __nv_bfloat16 g_xl[(size_t)SEQ * DM];
__device__ __nv_bfloat16 g_wth[(size_t)H * NE3 * DM];   // w transposed: [h][n][k]
__device__ __nv_bfloat16 g_wtl[(size_t)H * NE3 * DM];
__device__ float         g_qkv[(size_t)H * SEQ * NE3];  // [h][s][3e]
__device__ __nv_bfloat16 g_qkvh[(size_t)H * SEQ * NE3];
__device__ __nv_bfloat16 g_qkvl[(size_t)H * SEQ * NE3];
__device__ __nv_bfloat16 g_vth[(size_t)H * E * SEQ];    // V^T: [h][e][t]
__device__ __nv_bfloat16 g_vtl[(size_t)H * E * SEQ];
__device__ float         g_scores[(size_t)H * SEQ * SEQ];
__device__ __nv_bfloat16 g_ph[(size_t)H * SEQ * SEQ];
__device__ __nv_bfloat16 g_pl[(size_t)H * SEQ * SEQ];

// ----------------- mma.sync bf16 batched GEMM (base ISA only) -----------------
// C[128m x 128n] = alpha * A * B^T ; A:[M][K] K-major (lda), B:[N][K] K-major (ldb)
// bf16 hi/lo pairs, 3-term split per k-step.
constexpr int BM = 128, BN = 128, BK = 32;
constexpr int PITCH = 40;                       // bf16 elems per smem row (64B data + 16B pad)
constexpr int TILE_BYTES  = 128 * PITCH * 2;    // 10240 B
constexpr int STAGE_BYTES = 4 * TILE_BYTES;     // Ah, Al, Bh, Bl = 40960 B
constexpr int NSTAGE = 3;

__device__ __forceinline__ uint32_t smem_u32(const void* p) {
    uint32_t a;
    asm("{ .reg .u64 t; cvta.to.shared.u64 t, %1; cvt.u32.u64 %0, t; }" : "=r"(a) : "l"(p));
    return a;
}

__device__ __forceinline__ void ld_tile(uint32_t dst, const __nv_bfloat16* src, int ld, int tid) {
    #pragma unroll
    for (int j = 0; j < 2; j++) {
        int idx = tid + j * 256;        // 512 16B-chunks: 128 rows x 4 chunks
        int row = idx >> 2, ch = idx & 3;
        uint32_t s = dst + row * (PITCH * 2) + ch * 16;
        const __nv_bfloat16* g = src + (size_t)row * ld + ch * 8;
        asm volatile("cp.async.cg.shared.global [%0], [%1], 16;" :: "r"(s), "l"(g));
    }
}

#define LDSM4(r, a)                                                              \
    asm volatile("ldmatrix.sync.aligned.m8n8.x4.shared.b16 {%0,%1,%2,%3}, [%4];" \
                 : "=r"((r)[0]), "=r"((r)[1]), "=r"((r)[2]), "=r"((r)[3]) : "r"(a))
#define MMA_BF16(d, a, b0, b1)                                                       \
    asm volatile("mma.sync.aligned.m16n8k16.row.col.f32.bf16.bf16.f32 "              \
                 "{%0,%1,%2,%3},{%4,%5,%6,%7},{%8,%9},{%0,%1,%2,%3};"                \
                 : "+f"((d)[0]), "+f"((d)[1]), "+f"((d)[2]), "+f"((d)[3])            \
                 : "r"((a)[0]), "r"((a)[1]), "r"((a)[2]), "r"((a)[3]), "r"(b0), "r"(b1))

__global__ void __launch_bounds__(256, 1)
gemm_bf16x3(const __nv_bfloat16* __restrict__ Ah, const __nv_bfloat16* __restrict__ Al,
            const __nv_bfloat16* __restrict__ Bh, const __nv_bfloat16* __restrict__ Bl,
            float* __restrict__ C,
            int K, int lda, int ldb, int ldc,
            long long aB, long long bB, long long cB, float alpha)
{
    extern __shared__ __align__(1024) char dsm[];
    const uint32_t base = smem_u32(dsm);

    const int tid = threadIdx.x;
    const int lane = tid & 31, wid = tid >> 5;
    const int wm = wid & 1;          // 2 warps over M: 64 rows each
    const int wn = wid >> 1;         // 4 warps over N: 32 cols each
    const int m0 = blockIdx.x * BM, n0 = blockIdx.y * BN;
    const long long z = blockIdx.z;

    const __nv_bfloat16* pAh = Ah + z * aB + (size_t)m0 * lda;
    const __nv_bfloat16* pAl = Al + z * aB + (size_t)m0 * lda;
    const __nv_bfloat16* pBh = Bh + z * bB + (size_t)n0 * ldb;
    const __nv_bfloat16* pBl = Bl + z * bB + (size_t)n0 * ldb;

    // per-thread invariant ldmatrix offsets (bytes)
    // A: lanes 0-7 -> m-rows 0-7 @k0 (frag a0), 8-15 -> m8-15 @k0 (a1),
    //    16-23 -> m0-7 @k8 (a2), 24-31 -> m8-15 @k8 (a3)
    const uint32_t a_row = (uint32_t)(wm * 64 + (lane & 15)) * (PITCH * 2);
    const uint32_t a_k   = (uint32_t)((lane >> 4) << 3) * 2;
    // B (stored [N][K]; plain ldmatrix yields the col-major fragment directly):
    //    lanes 0-7 -> n0-7 @k0 (b0), 8-15 -> n0-7 @k8 (b1),
    //    16-23 -> n8-15 @k0, 24-31 -> n8-15 @k8
    const uint32_t b_row = (uint32_t)(wn * 32 + ((lane >> 4) << 3) + (lane & 7)) * (PITCH * 2);
    const uint32_t b_k   = (uint32_t)(((lane >> 3) & 1) << 3) * 2;

    float acc[4][4][4] = {};

    const int nIter = K >> 5;
    // warmup: stages 0..NSTAGE-2
    #pragma unroll
    for (int s = 0; s < NSTAGE - 1; s++) {
        uint32_t sb = base + s * STAGE_BYTES;
        ld_tile(sb,                  pAh + s * BK, lda, tid);
        ld_tile(sb + TILE_BYTES,     pAl + s * BK, lda, tid);
        ld_tile(sb + 2 * TILE_BYTES, pBh + s * BK, ldb, tid);
        ld_tile(sb + 3 * TILE_BYTES, pBl + s * BK, ldb, tid);
        asm volatile("cp.async.commit_group;" ::: "memory");
    }

    for (int i = 0; i < nIter; i++) {
        asm volatile("cp.async.wait_group %0;" :: "n"(NSTAGE - 2) : "memory");
        __syncthreads();

        // prefetch chunk i+NSTAGE-1 into the buffer consumed at iter i-1
        const int c = i + NSTAGE - 1;
        if (c < nIter) {
            uint32_t sb = base + (c % NSTAGE) * STAGE_BYTES;
            ld_tile(sb,                  pAh + c * BK, lda, tid);
            ld_tile(sb + TILE_BYTES,     pAl + c * BK, lda, tid);
            ld_tile(sb + 2 * TILE_BYTES, pBh + c * BK, ldb, tid);
            ld_tile(sb + 3 * TILE_BYTES, pBl + c * BK, ldb, tid);
        }
        asm volatile("cp.async.commit_group;" ::: "memory");   // always (uniform accounting)

        const uint32_t sb   = base + (i % NSTAGE) * STAGE_BYTES;
        const uint32_t sA_h = sb;
        const uint32_t sA_l = sb + TILE_BYTES;
        const uint32_t sB_h = sb + 2 * TILE_BYTES;
        const uint32_t sB_l = sb + 3 * TILE_BYTES;

        #pragma unroll
        for (int kk = 0; kk < 2; kk++) {       // two k16 steps per BK=32
            const uint32_t ka = (uint32_t)(kk * 16) * 2 + a_k;
            const uint32_t kb = (uint32_t)(kk * 16) * 2 + b_k;
            uint32_t fah[4][4], fal[4][4], fbh[2][4], fbl[2][4];
            #pragma unroll
            for (int mt = 0; mt < 4; mt++) {
                uint32_t o = a_row + (uint32_t)mt * 16 * (PITCH * 2) + ka;
                LDSM4(fah[mt], sA_h + o);
                LDSM4(fal[mt], sA_l + o);
            }
            #pragma unroll
            for (int nr = 0; nr < 2; nr++) {
                uint32_t o = b_row + (uint32_t)nr * 16 * (PITCH * 2) + kb;
                LDSM4(fbh[nr], sB_h + o);
                LDSM4(fbl[nr], sB_l + o);
            }
            #pragma unroll
            for (int mt = 0; mt < 4; mt++) {
                #pragma unroll
                for (int nt = 0; nt < 4; nt++) {
                    const int nr = nt >> 1, p = (nt & 1) * 2;
                    MMA_BF16(acc[mt][nt], fah[mt], fbh[nr][p], fbh[nr][p + 1]);
                    MMA_BF16(acc[mt][nt], fah[mt], fbl[nr][p], fbl[nr][p + 1]);
                    MMA_BF16(acc[mt][nt], fal[mt], fbh[nr][p], fbh[nr][p + 1]);
                }
            }
        }
    }

    // epilogue
    float* crow = C + z * cB;
    const int er = m0 + wm * 64 + (lane >> 2);
    const int ec = n0 + wn * 32 + (lane & 3) * 2;
    #pragma unroll
    for (int mt = 0; mt < 4; mt++) {
        #pragma unroll
        for (int nt = 0; nt < 4; nt++) {
            const size_t r0 = (size_t)(er + mt * 16) * ldc + ec + nt * 8;
            float2 v0 = { acc[mt][nt][0] * alpha, acc[mt][nt][1] * alpha };
            float2 v1 = { acc[mt][nt][2] * alpha, acc[mt][nt][3] * alpha };
            *reinterpret_cast<float2*>(crow + r0)               = v0;
            *reinterpret_cast<float2*>(crow + r0 + 8 * ldc)     = v1;
        }
    }
}

// ----------------- fp32 -> bf16 hi/lo split -----------------
__global__ void split_f32(const float* __restrict__ s,
                          __nv_bfloat16* __restrict__ hi, __nv_bfloat16* __restrict__ lo,
                          size_t nelem)
{
    size_t i = (size_t)blockIdx.x * blockDim.x + threadIdx.x;
    size_t stride = (size_t)gridDim.x * blockDim.x;
    for (; i < nelem; i += stride) {
        float v = s[i];
        __nv_bfloat16 h = __float2bfloat16(v);
        hi[i] = h;
        lo[i] = __float2bfloat16(v - __bfloat162float(h));
    }
}

// ----------------- transpose + split: dst[c][r] = src[r][c] -----------------
__global__ void trans_split(const float* __restrict__ src,
                            __nv_bfloat16* __restrict__ th, __nv_bfloat16* __restrict__ tl,
                            int srows, int scols, long long sBatch, long long dBatch, int soff)
{
    __shared__ float t[32][33];
    const float* s = src + (size_t)blockIdx.z * sBatch + soff;
    int r0 = blockIdx.x * 32, c0 = blockIdx.y * 32;
    int tx = threadIdx.x, ty = threadIdx.y;   // 32 x 8
    #pragma unroll
    for (int j = 0; j < 32; j += 8)
        t[ty + j][tx] = s[(size_t)(r0 + ty + j) * scols + c0 + tx];
    __syncthreads();
    size_t db = (size_t)blockIdx.z * dBatch;
    #pragma unroll
    for (int j = 0; j < 32; j += 8) {
        float v = t[tx][ty + j];
        __nv_bfloat16 h = __float2bfloat16(v);
        size_t o = db + (size_t)(c0 + ty + j) * srows + r0 + tx;
        th[o] = h;
        tl[o] = __float2bfloat16(v - __bfloat162float(h));
    }
}

// ----------------- softmax rows -> bf16 hi/lo probs -----------------
__global__ void softmax_split(const float* __restrict__ sc,
                              __nv_bfloat16* __restrict__ ph, __nv_bfloat16* __restrict__ pl)
{
    size_t row = blockIdx.x;
    const float* p = sc + row * (size_t)SEQ;
    const int tid = threadIdx.x, lane = tid & 31, wid = tid >> 5;
    __shared__ float red[8];
    __shared__ float bv;

    float ev[8];
    float mx = -1e30f;
    #pragma unroll
    for (int j = 0; j < 8; j++) { ev[j] = p[tid + j * 256]; mx = fmaxf(mx, ev[j]); }
    #pragma unroll
    for (int o = 16; o; o >>= 1) mx = fmaxf(mx, __shfl_xor_sync(0xffffffffu, mx, o));
    if (lane == 0) red[wid] = mx;
    __syncthreads();
    if (tid == 0) {
        float m = red[0];
        #pragma unroll
        for (int i = 1; i < 8; i++) m = fmaxf(m, red[i]);
        bv = m;
    }
    __syncthreads();
    mx = bv;

    float s = 0.0f;
    #pragma unroll
    for (int j = 0; j < 8; j++) { ev[j] = __expf(ev[j] - mx); s += ev[j]; }
    #pragma unroll
    for (int o = 16; o; o >>= 1) s += __shfl_xor_sync(0xffffffffu, s, o);
    if (lane == 0) red[wid] = s;
    __syncthreads();
    if (tid == 0) {
        float t = 0.0f;
        #pragma unroll
        for (int i = 0; i < 8; i++) t += red[i];
        bv = 1.0f / t;
    }
    __syncthreads();
    const float inv = bv;
    size_t rb = row * (size_t)SEQ;
    #pragma unroll
    for (int j = 0; j < 8; j++) {
        float v = ev[j] * inv;
        __nv_bfloat16 h = __float2bfloat16(v);
        ph[rb + tid + j * 256] = h;
        pl[rb + tid + j * 256] = __float2bfloat16(v - __bfloat162float(h));
    }
}

// ----------------- launch -----------------
extern "C" void kernel_launch(void* const* d_in, const int* in_sizes, int n_in,
                              void* d_out, int out_size)
{
    const float* x = (const float*)d_in[0];   // [S, D]
    const float* w = (const float*)d_in[1];   // [H, D, 3E]
    float* out = (float*)d_out;               // [S, H*E]

    __nv_bfloat16 *xh, *xl, *wth, *wtl, *qkvh, *qkvl, *vth, *vtl, *ph, *pl;
    float *qkv, *scores;
    cudaGetSymbolAddress((void**)&xh, g_xh);
    cudaGetSymbolAddress((void**)&xl, g_xl);
    cudaGetSymbolAddress((void**)&wth, g_wth);
    cudaGetSymbolAddress((void**)&wtl, g_wtl);
    cudaGetSymbolAddress((void**)&qkv, g_qkv);
    cudaGetSymbolAddress((void**)&qkvh, g_qkvh);
    cudaGetSymbolAddress((void**)&qkvl, g_qkvl);
    cudaGetSymbolAddress((void**)&vth, g_vth);
    cudaGetSymbolAddress((void**)&vtl, g_vtl);
    cudaGetSymbolAddress((void**)&scores, g_scores);
    cudaGetSymbolAddress((void**)&ph, g_ph);
    cudaGetSymbolAddress((void**)&pl, g_pl);

    const int smemB = NSTAGE * STAGE_BYTES;   // 122880
    cudaFuncSetAttribute(gemm_bf16x3, cudaFuncAttributeMaxDynamicSharedMemorySize, smemB);

    const float inv_sqrt_e = 0.08838834764831845f;  // 1/sqrt(128)

    // split x
    split_f32<<<4096, 256>>>(x, xh, xl, (size_t)SEQ * DM);
    // transpose+split w: [h][k=2048][n=384] -> wt[h][n][k]
    trans_split<<<dim3(DM / 32, NE3 / 32, H), dim3(32, 8)>>>(
        w, wth, wtl, DM, NE3, (long long)DM * NE3, (long long)NE3 * DM, 0);

    // 1) qkv[h][s][n] = x @ w[h]
    gemm_bf16x3<<<dim3(SEQ / BM, NE3 / BN, H), 256, smemB>>>(
        xh, xl, wth, wtl, qkv,
        DM, DM, DM, NE3,
        0LL, (long long)NE3 * DM, (long long)SEQ * NE3, 1.0f);

    // split qkv (for Q, K)
    split_f32<<<4096, 256>>>(qkv, qkvh, qkvl, (size_t)H * SEQ * NE3);
    // transpose+split V part: qkv[h][s][256+e] -> vt[h][e][t]
    trans_split<<<dim3(SEQ / 32, E / 32, H), dim3(32, 8)>>>(
        qkv, vth, vtl, SEQ, NE3, (long long)SEQ * NE3, (long long)E * SEQ, 2 * E);

    // 2) scores[h][s][t] = (Q @ K^T) / sqrt(E)
    gemm_bf16x3<<<dim3(SEQ / BM, SEQ / BN, H), 256, smemB>>>(
        qkvh, qkvl, qkvh + E, qkvl + E, scores,
        E, NE3, NE3, SEQ,
        (long long)SEQ * NE3, (long long)SEQ * NE3, (long long)SEQ * SEQ, inv_sqrt_e);

    // 3) softmax -> bf16 hi/lo probs
    softmax_split<<<H * SEQ, 256>>>(scores, ph, pl);

    // 4) out[s][h*E + e] = P @ V  (B = V^T, K-major)
    gemm_bf16x3<<<dim3(SEQ / BM, E / BN, H), 256, smemB>>>(
        ph, pl, vth, vtl, out,
        SEQ, SEQ, SEQ, DM,
        (long long)SEQ * SEQ, (long long)E * SEQ, (long long)E, 1.0f);
}

// round 7
// speedup vs baseline: 5.4361x; 1.2564x over previous
#include <cuda_runtime.h>
#include <cuda_bf16.h>
#include <cstdint>
#include <math.h>

#define SEQ 2048
#define DM 2048
#define H 16
#define E 128
#define NE3 384

// ----------------- scratch (static device allocations) -----------------
__device__ __nv_bfloat16 g_xh[(size_t)SEQ * DM];
__device__ __nv_bfloat16 g_xl[(size_t)SEQ * DM];
__device__ __nv_bfloat16 g_wth[(size_t)H * NE3 * DM];    // w transposed: [h][n][k]
__device__ __nv_bfloat16 g_wtl[(size_t)H * NE3 * DM];
__device__ __nv_bfloat16 g_qkh[(size_t)H * SEQ * 256];   // [h][s][Q(0:128)|K(128:256)] hi
__device__ __nv_bfloat16 g_qkl[(size_t)H * SEQ * 256];   // lo
__device__ __nv_bfloat16 g_vth[(size_t)H * E * SEQ];     // V^T: [h][e][t] hi
__device__ __nv_bfloat16 g_vtl[(size_t)H * E * SEQ];     // lo

__device__ __forceinline__ uint32_t smem_u32(const void* p) {
    uint32_t a;
    asm("{ .reg .u64 t; cvta.to.shared.u64 t, %1; cvt.u32.u64 %0, t; }" : "=r"(a) : "l"(p));
    return a;
}
__device__ __forceinline__ float fexp2(float x) {
    float r;
    asm("ex2.approx.f32 %0, %1;" : "=f"(r) : "f"(x));
    return r;
}

#define LDSM4(r, a)                                                              \
    asm volatile("ldmatrix.sync.aligned.m8n8.x4.shared.b16 {%0,%1,%2,%3}, [%4];" \
                 : "=r"((r)[0]), "=r"((r)[1]), "=r"((r)[2]), "=r"((r)[3]) : "r"(a))
#define MMA_BF16(d, a, b0, b1)                                                       \
    asm volatile("mma.sync.aligned.m16n8k16.row.col.f32.bf16.bf16.f32 "              \
                 "{%0,%1,%2,%3},{%4,%5,%6,%7},{%8,%9},{%0,%1,%2,%3};"                \
                 : "+f"((d)[0]), "+f"((d)[1]), "+f"((d)[2]), "+f"((d)[3])            \
                 : "r"((a)[0]), "r"((a)[1]), "r"((a)[2]), "r"((a)[3]), "r"(b0), "r"(b1))

__device__ __forceinline__ uint32_t pack_split(float a, float b, uint32_t& lo) {
    __nv_bfloat16 ha = __float2bfloat16(a), hb = __float2bfloat16(b);
    __nv_bfloat16 la = __float2bfloat16(a - __bfloat162float(ha));
    __nv_bfloat16 lb = __float2bfloat16(b - __bfloat162float(hb));
    lo = (uint32_t)__bfloat16_as_ushort(la) | ((uint32_t)__bfloat16_as_ushort(lb) << 16);
    return (uint32_t)__bfloat16_as_ushort(ha) | ((uint32_t)__bfloat16_as_ushort(hb) << 16);
}

// ================= GEMM: C(bf16 hi/lo) = A * B^T, bf16x3 =================
// A:[M][K] K-major (lda), B:[N][K] K-major (ldb). Cols < thr scaled by alpha0.
constexpr int BM = 128, BN = 128, BK = 32;
constexpr int PITCH = 40;                       // bf16 elems per smem row
constexpr int TILE_BYTES  = 128 * PITCH * 2;    // 10240 B
constexpr int STAGE_BYTES = 4 * TILE_BYTES;     // Ah, Al, Bh, Bl
constexpr int NSTAGE = 3;

__device__ __forceinline__ void ld_tile(uint32_t dst, const __nv_bfloat16* src, int ld, int tid) {
    #pragma unroll
    for (int j = 0; j < 2; j++) {
        int idx = tid + j * 256;
        int row = idx >> 2, ch = idx & 3;
        uint32_t s = dst + row * (PITCH * 2) + ch * 16;
        const __nv_bfloat16* g = src + (size_t)row * ld + ch * 8;
        asm volatile("cp.async.cg.shared.global [%0], [%1], 16;" :: "r"(s), "l"(g));
    }
}

__global__ void __launch_bounds__(256, 1)
gemm_bf16x3(const __nv_bfloat16* __restrict__ Ah, const __nv_bfloat16* __restrict__ Al,
            const __nv_bfloat16* __restrict__ Bh, const __nv_bfloat16* __restrict__ Bl,
            __nv_bfloat16* __restrict__ Ch, __nv_bfloat16* __restrict__ Cl,
            int K, int lda, int ldb, int ldc,
            long long aB, long long bB, long long cB, float alpha0, int thr)
{
    extern __shared__ __align__(1024) char dsm[];
    const uint32_t base = smem_u32(dsm);

    const int tid = threadIdx.x;
    const int lane = tid & 31, wid = tid >> 5;
    const int wm = wid & 1;
    const int wn = wid >> 1;
    const int m0 = blockIdx.x * BM, n0 = blockIdx.y * BN;
    const long long z = blockIdx.z;

    const __nv_bfloat16* pAh = Ah + z * aB + (size_t)m0 * lda;
    const __nv_bfloat16* pAl = Al + z * aB + (size_t)m0 * lda;
    const __nv_bfloat16* pBh = Bh + z * bB + (size_t)n0 * ldb;
    const __nv_bfloat16* pBl = Bl + z * bB + (size_t)n0 * ldb;

    const uint32_t a_row = (uint32_t)(wm * 64 + (lane & 15)) * (PITCH * 2);
    const uint32_t a_k   = (uint32_t)((lane >> 4) << 3) * 2;
    const uint32_t b_row = (uint32_t)(wn * 32 + ((lane >> 4) << 3) + (lane & 7)) * (PITCH * 2);
    const uint32_t b_k   = (uint32_t)(((lane >> 3) & 1) << 3) * 2;

    float acc[4][4][4] = {};

    const int nIter = K >> 5;
    #pragma unroll
    for (int s = 0; s < NSTAGE - 1; s++) {
        uint32_t sb = base + s * STAGE_BYTES;
        ld_tile(sb,                  pAh + s * BK, lda, tid);
        ld_tile(sb + TILE_BYTES,     pAl + s * BK, lda, tid);
        ld_tile(sb + 2 * TILE_BYTES, pBh + s * BK, ldb, tid);
        ld_tile(sb + 3 * TILE_BYTES, pBl + s * BK, ldb, tid);
        asm volatile("cp.async.commit_group;" ::: "memory");
    }

    for (int i = 0; i < nIter; i++) {
        asm volatile("cp.async.wait_group %0;" :: "n"(NSTAGE - 2) : "memory");
        __syncthreads();

        const int c = i + NSTAGE - 1;
        if (c < nIter) {
            uint32_t sb = base + (c % NSTAGE) * STAGE_BYTES;
            ld_tile(sb,                  pAh + c * BK, lda, tid);
            ld_tile(sb + TILE_BYTES,     pAl + c * BK, lda, tid);
            ld_tile(sb + 2 * TILE_BYTES, pBh + c * BK, ldb, tid);
            ld_tile(sb + 3 * TILE_BYTES, pBl + c * BK, ldb, tid);
        }
        asm volatile("cp.async.commit_group;" ::: "memory");

        const uint32_t sb   = base + (i % NSTAGE) * STAGE_BYTES;
        const uint32_t sA_h = sb;
        const uint32_t sA_l = sb + TILE_BYTES;
        const uint32_t sB_h = sb + 2 * TILE_BYTES;
        const uint32_t sB_l = sb + 3 * TILE_BYTES;

        #pragma unroll
        for (int kk = 0; kk < 2; kk++) {
            const uint32_t ka = (uint32_t)(kk * 16) * 2 + a_k;
            const uint32_t kb = (uint32_t)(kk * 16) * 2 + b_k;
            uint32_t fah[4][4], fal[4][4], fbh[2][4], fbl[2][4];
            #pragma unroll
            for (int mt = 0; mt < 4; mt++) {
                uint32_t o = a_row + (uint32_t)mt * 16 * (PITCH * 2) + ka;
                LDSM4(fah[mt], sA_h + o);
                LDSM4(fal[mt], sA_l + o);
            }
            #pragma unroll
            for (int nr = 0; nr < 2; nr++) {
                uint32_t o = b_row + (uint32_t)nr * 16 * (PITCH * 2) + kb;
                LDSM4(fbh[nr], sB_h + o);
                LDSM4(fbl[nr], sB_l + o);
            }
            #pragma unroll
            for (int mt = 0; mt < 4; mt++) {
                #pragma unroll
                for (int nt = 0; nt < 4; nt++) {
                    const int nr = nt >> 1, p = (nt & 1) * 2;
                    MMA_BF16(acc[mt][nt], fah[mt], fbh[nr][p], fbh[nr][p + 1]);
                    MMA_BF16(acc[mt][nt], fah[mt], fbl[nr][p], fbl[nr][p + 1]);
                    MMA_BF16(acc[mt][nt], fal[mt], fbh[nr][p], fbh[nr][p + 1]);
                }
            }
        }
    }

    // epilogue: scale (cols < thr) and write bf16 hi/lo pairs
    __nv_bfloat16* ch = Ch + z * cB;
    __nv_bfloat16* cl = Cl + z * cB;
    const int er = m0 + wm * 64 + (lane >> 2);
    const int ecb = n0 + wn * 32 + (lane & 3) * 2;
    #pragma unroll
    for (int mt = 0; mt < 4; mt++) {
        #pragma unroll
        for (int nt = 0; nt < 4; nt++) {
            const int col = ecb + nt * 8;
            const float a = (col < thr) ? alpha0 : 1.0f;
            const size_t o0 = (size_t)(er + mt * 16) * ldc + col;
            const size_t o1 = o0 + 8 * (size_t)ldc;
            uint32_t lo, hi;
            hi = pack_split(acc[mt][nt][0] * a, acc[mt][nt][1] * a, lo);
            *reinterpret_cast<uint32_t*>(ch + o0) = hi;
            *reinterpret_cast<uint32_t*>(cl + o0) = lo;
            hi = pack_split(acc[mt][nt][2] * a, acc[mt][nt][3] * a, lo);
            *reinterpret_cast<uint32_t*>(ch + o1) = hi;
            *reinterpret_cast<uint32_t*>(cl + o1) = lo;
        }
    }
}

// ================= fused flash attention =================
// grid (S/128, H), 256 thr. Q/K from g_qk{h,l} [h][s][256], V^T from g_vt{h,l} [h][e][t].
// smem: Qh Ql Kh Kl Vh Vl tiles, each 128x128 bf16, XOR-swizzled 256B rows.
constexpr int FT = 32768;                 // bytes per tile
#define FSWZ(row, c) ((uint32_t)((row) * 256 + (((c) ^ ((row) & 7)) << 4)))

__global__ void __launch_bounds__(256, 1)
flash_attn(const __nv_bfloat16* __restrict__ qk_h, const __nv_bfloat16* __restrict__ qk_l,
           const __nv_bfloat16* __restrict__ vt_h, const __nv_bfloat16* __restrict__ vt_l,
           float* __restrict__ out)
{
    extern __shared__ __align__(1024) char fsm[];
    const uint32_t sQh = smem_u32(fsm);
    const uint32_t sQl = sQh + FT, sKh = sQh + 2 * FT, sKl = sQh + 3 * FT;
    const uint32_t sVh = sQh + 4 * FT, sVl = sQh + 5 * FT;

    const int tid = threadIdx.x, lane = tid & 31, wr = tid >> 5;
    const int q0 = blockIdx.x * 128;
    const int h = blockIdx.y;
    const size_t qkB = (size_t)h * SEQ * 256;
    const size_t vB  = (size_t)h * E * SEQ;

    // tile loader: 128 rows x 128 bf16 cols; src row stride = ld elements
    #define FLD(dst, src, ld)                                                             \
        do {                                                                              \
            _Pragma("unroll")                                                             \
            for (int j_ = 0; j_ < 8; j_++) {                                              \
                int idx_ = tid + j_ * 256;                                                \
                int row_ = idx_ >> 4, c_ = idx_ & 15;                                     \
                uint32_t d_ = (dst) + FSWZ(row_, c_);                                     \
                const __nv_bfloat16* g_ = (src) + (size_t)row_ * (ld) + c_ * 8;           \
                asm volatile("cp.async.cg.shared.global [%0], [%1], 16;" :: "r"(d_), "l"(g_)); \
            }                                                                             \
        } while (0)

    // warmup: Q + K0
    FLD(sQh, qk_h + qkB + (size_t)q0 * 256, 256);
    FLD(sQl, qk_l + qkB + (size_t)q0 * 256, 256);
    FLD(sKh, qk_h + qkB + 128, 256);
    FLD(sKl, qk_l + qkB + 128, 256);
    asm volatile("cp.async.commit_group;" ::: "memory");

    float o[16][4] = {};
    float m01 = -1e30f, m23 = -1e30f, l01 = 0.f, l23 = 0.f;
    const float LOG2E = 1.4426950408889634f;

    const int qrow = wr * 16 + (lane & 15);
    const int nrow = ((lane >> 4) << 3) + (lane & 7);

    for (int j = 0; j < 16; j++) {
        asm volatile("cp.async.wait_group 0;" ::: "memory");
        __syncthreads();    // K_j ready; all warps done with V_{j-1}

        // prefetch V_j
        FLD(sVh, vt_h + vB + j * 128, SEQ);
        FLD(sVl, vt_l + vB + j * 128, SEQ);
        asm volatile("cp.async.commit_group;" ::: "memory");

        // ---- S = Q * K_j^T  (bf16x3) ----
        float s[16][4] = {};
        #pragma unroll
        for (int ks = 0; ks < 8; ks++) {
            const int cA = ks * 2 + (lane >> 4);
            const uint32_t aoff = FSWZ(qrow, cA);
            uint32_t qh_f[4], ql_f[4];
            LDSM4(qh_f, sQh + aoff);
            LDSM4(ql_f, sQl + aoff);
            const int cB = ks * 2 + ((lane >> 3) & 1);
            #pragma unroll
            for (int np = 0; np < 8; np++) {
                const int br = np * 16 + nrow;
                const uint32_t boff = FSWZ(br, cB);
                uint32_t kh_f[4], kl_f[4];
                LDSM4(kh_f, sKh + boff);
                LDSM4(kl_f, sKl + boff);
                MMA_BF16(s[2 * np],     qh_f, kh_f[0], kh_f[1]);
                MMA_BF16(s[2 * np + 1], qh_f, kh_f[2], kh_f[3]);
                MMA_BF16(s[2 * np],     qh_f, kl_f[0], kl_f[1]);
                MMA_BF16(s[2 * np + 1], qh_f, kl_f[2], kl_f[3]);
                MMA_BF16(s[2 * np],     ql_f, kh_f[0], kh_f[1]);
                MMA_BF16(s[2 * np + 1], ql_f, kh_f[2], kh_f[3]);
            }
        }

        asm volatile("cp.async.wait_group 0;" ::: "memory");
        __syncthreads();    // V_j ready; all warps done reading K_j

        // prefetch K_{j+1}
        if (j + 1 < 16) {
            FLD(sKh, qk_h + qkB + (size_t)(j + 1) * 128 * 256 + 128, 256);
            FLD(sKl, qk_l + qkB + (size_t)(j + 1) * 128 * 256 + 128, 256);
        }
        asm volatile("cp.async.commit_group;" ::: "memory");

        // ---- online softmax ----
        float nm0 = m01, nm1 = m23;
        #pragma unroll
        for (int nt = 0; nt < 16; nt++) {
            nm0 = fmaxf(nm0, fmaxf(s[nt][0], s[nt][1]));
            nm1 = fmaxf(nm1, fmaxf(s[nt][2], s[nt][3]));
        }
        nm0 = fmaxf(nm0, __shfl_xor_sync(0xffffffffu, nm0, 1));
        nm0 = fmaxf(nm0, __shfl_xor_sync(0xffffffffu, nm0, 2));
        nm1 = fmaxf(nm1, __shfl_xor_sync(0xffffffffu, nm1, 1));
        nm1 = fmaxf(nm1, __shfl_xor_sync(0xffffffffu, nm1, 2));
        const float sc0 = fexp2((m01 - nm0) * LOG2E);
        const float sc1 = fexp2((m23 - nm1) * LOG2E);
        m01 = nm0; m23 = nm1;
        float rs0 = 0.f, rs1 = 0.f;
        #pragma unroll
        for (int nt = 0; nt < 16; nt++) {
            s[nt][0] = fexp2((s[nt][0] - m01) * LOG2E);
            s[nt][1] = fexp2((s[nt][1] - m01) * LOG2E);
            s[nt][2] = fexp2((s[nt][2] - m23) * LOG2E);
            s[nt][3] = fexp2((s[nt][3] - m23) * LOG2E);
            rs0 += s[nt][0] + s[nt][1];
            rs1 += s[nt][2] + s[nt][3];
        }
        rs0 += __shfl_xor_sync(0xffffffffu, rs0, 1);
        rs0 += __shfl_xor_sync(0xffffffffu, rs0, 2);
        rs1 += __shfl_xor_sync(0xffffffffu, rs1, 1);
        rs1 += __shfl_xor_sync(0xffffffffu, rs1, 2);
        l01 = l01 * sc0 + rs0;
        l23 = l23 * sc1 + rs1;
        #pragma unroll
        for (int nt = 0; nt < 16; nt++) {
            o[nt][0] *= sc0; o[nt][1] *= sc0;
            o[nt][2] *= sc1; o[nt][3] *= sc1;
        }

        // ---- O += P * V  (bf16x3) ----
        #pragma unroll
        for (int ks = 0; ks < 8; ks++) {
            uint32_t ah_f[4], al_f[4];
            ah_f[0] = pack_split(s[2 * ks][0],     s[2 * ks][1],     al_f[0]);
            ah_f[1] = pack_split(s[2 * ks][2],     s[2 * ks][3],     al_f[1]);
            ah_f[2] = pack_split(s[2 * ks + 1][0], s[2 * ks + 1][1], al_f[2]);
            ah_f[3] = pack_split(s[2 * ks + 1][2], s[2 * ks + 1][3], al_f[3]);
            const int cV = ks * 2 + ((lane >> 3) & 1);
            #pragma unroll
            for (int ep = 0; ep < 8; ep++) {
                const int vr = ep * 16 + nrow;
                const uint32_t voff = FSWZ(vr, cV);
                uint32_t vh_f[4], vl_f[4];
                LDSM4(vh_f, sVh + voff);
                LDSM4(vl_f, sVl + voff);
                MMA_BF16(o[2 * ep],     ah_f, vh_f[0], vh_f[1]);
                MMA_BF16(o[2 * ep + 1], ah_f, vh_f[2], vh_f[3]);
                MMA_BF16(o[2 * ep],     ah_f, vl_f[0], vl_f[1]);
                MMA_BF16(o[2 * ep + 1], ah_f, vl_f[2], vl_f[3]);
                MMA_BF16(o[2 * ep],     al_f, vh_f[0], vh_f[1]);
                MMA_BF16(o[2 * ep + 1], al_f, vh_f[2], vh_f[3]);
            }
        }
    }

    // epilogue
    const float inv0 = 1.0f / l01, inv1 = 1.0f / l23;
    const int row = q0 + wr * 16 + (lane >> 2);
    float* po = out + (size_t)row * DM + h * 128 + (lane & 3) * 2;
    #pragma unroll
    for (int nt = 0; nt < 16; nt++) {
        float2 v0 = { o[nt][0] * inv0, o[nt][1] * inv0 };
        float2 v1 = { o[nt][2] * inv1, o[nt][3] * inv1 };
        *reinterpret_cast<float2*>(po + nt * 8) = v0;
        *reinterpret_cast<float2*>(po + 8 * DM + nt * 8) = v1;
    }
}

// ----------------- fp32 -> bf16 hi/lo split (x) -----------------
__global__ void split_f32(const float* __restrict__ s,
                          __nv_bfloat16* __restrict__ hi, __nv_bfloat16* __restrict__ lo,
                          size_t nelem)
{
    size_t i = (size_t)blockIdx.x * blockDim.x + threadIdx.x;
    size_t stride = (size_t)gridDim.x * blockDim.x;
    for (size_t p = i * 4; p < nelem; p += stride * 4) {
        float4 v = *reinterpret_cast<const float4*>(s + p);
        uint32_t l0, l1;
        uint32_t h0 = pack_split(v.x, v.y, l0);
        uint32_t h1 = pack_split(v.z, v.w, l1);
        *reinterpret_cast<uint32_t*>(hi + p)     = h0;
        *reinterpret_cast<uint32_t*>(hi + p + 2) = h1;
        *reinterpret_cast<uint32_t*>(lo + p)     = l0;
        *reinterpret_cast<uint32_t*>(lo + p + 2) = l1;
    }
}

// ----------------- transpose + split: dst[c][r] = src[r][c] -----------------
__global__ void trans_split(const float* __restrict__ src,
                            __nv_bfloat16* __restrict__ th, __nv_bfloat16* __restrict__ tl,
                            int srows, int scols, long long sBatch, long long dBatch, int soff)
{
    __shared__ float t[32][33];
    const float* s = src + (size_t)blockIdx.z * sBatch + soff;
    int r0 = blockIdx.x * 32, c0 = blockIdx.y * 32;
    int tx = threadIdx.x, ty = threadIdx.y;
    #pragma unroll
    for (int j = 0; j < 32; j += 8)
        t[ty + j][tx] = s[(size_t)(r0 + ty + j) * scols + c0 + tx];
    __syncthreads();
    size_t db = (size_t)blockIdx.z * dBatch;
    #pragma unroll
    for (int j = 0; j < 32; j += 8) {
        float v = t[tx][ty + j];
        __nv_bfloat16 hv = __float2bfloat16(v);
        size_t o = db + (size_t)(c0 + ty + j) * srows + r0 + tx;
        th[o] = hv;
        tl[o] = __float2bfloat16(v - __bfloat162float(hv));
    }
}

// ----------------- launch -----------------
extern "C" void kernel_launch(void* const* d_in, const int* in_sizes, int n_in,
                              void* d_out, int out_size)
{
    const float* x = (const float*)d_in[0];   // [S, D]
    const float* w = (const float*)d_in[1];   // [H, D, 3E]
    float* out = (float*)d_out;               // [S, H*E]

    __nv_bfloat16 *xh, *xl, *wth, *wtl, *qkh, *qkl, *vth, *vtl;
    cudaGetSymbolAddress((void**)&xh, g_xh);
    cudaGetSymbolAddress((void**)&xl, g_xl);
    cudaGetSymbolAddress((void**)&wth, g_wth);
    cudaGetSymbolAddress((void**)&wtl, g_wtl);
    cudaGetSymbolAddress((void**)&qkh, g_qkh);
    cudaGetSymbolAddress((void**)&qkl, g_qkl);
    cudaGetSymbolAddress((void**)&vth, g_vth);
    cudaGetSymbolAddress((void**)&vtl, g_vtl);

    const int smemG = NSTAGE * STAGE_BYTES;   // 122880
    cudaFuncSetAttribute(gemm_bf16x3, cudaFuncAttributeMaxDynamicSharedMemorySize, smemG);
    const int smemF = 6 * FT;                 // 196608
    cudaFuncSetAttribute(flash_attn, cudaFuncAttributeMaxDynamicSharedMemorySize, smemF);

    const float inv_sqrt_e = 0.08838834764831845f;  // 1/sqrt(128)

    // prepass
    split_f32<<<2048, 256>>>(x, xh, xl, (size_t)SEQ * DM);
    trans_split<<<dim3(DM / 32, NE3 / 32, H), dim3(32, 8)>>>(
        w, wth, wtl, DM, NE3, (long long)DM * NE3, (long long)NE3 * DM, 0);

    // 1a) QK: qk[h][s][0:256] = x @ w[h][:, 0:256], Q cols pre-scaled by 1/sqrt(E)
    gemm_bf16x3<<<dim3(SEQ / BM, 256 / BN, H), 256, smemG>>>(
        xh, xl, wth, wtl, qkh, qkl,
        DM, DM, DM, 256,
        0LL, (long long)NE3 * DM, (long long)SEQ * 256, inv_sqrt_e, 128);

    // 1b) V^T: vt[h][e][t] = Wv^T @ x^T  (A = wt rows 256..383, B = x)
    gemm_bf16x3<<<dim3(E / BM, SEQ / BN, H), 256, smemG>>>(
        wth + (size_t)256 * DM, wtl + (size_t)256 * DM, xh, xl, vth, vtl,
        DM, DM, DM, SEQ,
        (long long)NE3 * DM, 0LL, (long long)E * SEQ, 1.0f, 0);

    // 2) fused attention
    flash_attn<<<dim3(SEQ / 128, H), 256, smemF>>>(qkh, qkl, vth, vtl, out);
}

// round 8
// speedup vs baseline: 5.9940x; 1.1026x over previous
#include <cuda_runtime.h>
#include <cuda_bf16.h>
#include <cstdint>
#include <math.h>

#define SEQ 2048
#define DM 2048
#define H 16
#define E 128
#define NE3 384

// ----------------- scratch (static device allocations) -----------------
__device__ __nv_bfloat16 g_xh[(size_t)SEQ * DM];
__device__ __nv_bfloat16 g_xl[(size_t)SEQ * DM];
__device__ __nv_bfloat16 g_wth[(size_t)H * NE3 * DM];    // w transposed: [h][n][k]
__device__ __nv_bfloat16 g_wtl[(size_t)H * NE3 * DM];
__device__ __nv_bfloat16 g_qkh[(size_t)H * SEQ * 256];   // [h][s][Q(0:128)|K(128:256)] hi
__device__ __nv_bfloat16 g_qkl[(size_t)H * SEQ * 256];   // lo
__device__ __nv_bfloat16 g_vth[(size_t)H * E * SEQ];     // V^T: [h][e][t] hi
__device__ __nv_bfloat16 g_vtl[(size_t)H * E * SEQ];     // lo

__device__ __forceinline__ uint32_t smem_u32(const void* p) {
    uint32_t a;
    asm("{ .reg .u64 t; cvta.to.shared.u64 t, %1; cvt.u32.u64 %0, t; }" : "=r"(a) : "l"(p));
    return a;
}
__device__ __forceinline__ float fexp2(float x) {
    float r;
    asm("ex2.approx.f32 %0, %1;" : "=f"(r) : "f"(x));
    return r;
}

#define LDSM4(r, a)                                                              \
    asm volatile("ldmatrix.sync.aligned.m8n8.x4.shared.b16 {%0,%1,%2,%3}, [%4];" \
                 : "=r"((r)[0]), "=r"((r)[1]), "=r"((r)[2]), "=r"((r)[3]) : "r"(a))
#define MMA_BF16(d, a, b0, b1)                                                       \
    asm volatile("mma.sync.aligned.m16n8k16.row.col.f32.bf16.bf16.f32 "              \
                 "{%0,%1,%2,%3},{%4,%5,%6,%7},{%8,%9},{%0,%1,%2,%3};"                \
                 : "+f"((d)[0]), "+f"((d)[1]), "+f"((d)[2]), "+f"((d)[3])            \
                 : "r"((a)[0]), "r"((a)[1]), "r"((a)[2]), "r"((a)[3]), "r"(b0), "r"(b1))

__device__ __forceinline__ uint32_t pack_split(float a, float b, uint32_t& lo) {
    __nv_bfloat16 ha = __float2bfloat16(a), hb = __float2bfloat16(b);
    __nv_bfloat16 la = __float2bfloat16(a - __bfloat162float(ha));
    __nv_bfloat16 lb = __float2bfloat16(b - __bfloat162float(hb));
    lo = (uint32_t)__bfloat16_as_ushort(la) | ((uint32_t)__bfloat16_as_ushort(lb) << 16);
    return (uint32_t)__bfloat16_as_ushort(ha) | ((uint32_t)__bfloat16_as_ushort(hb) << 16);
}

// ================= GEMM: C(bf16 hi/lo) = A * B^T, bf16x3 =================
// A:[M][K] K-major (lda), B:[N][K] K-major (ldb). Cols < thr scaled by alpha0.
// Tiles 128x32 bf16 = 8KB, conflict-free via additive chunk swizzle (no padding):
// 16B-chunk c at row r stored at chunk' = (c + (r>>1)) & 3.
// Bank-group of (r, c') = (4r + c') mod 8 -> distinct across any 8 consecutive rows.
constexpr int BM = 128, BN = 128, BK = 32;
constexpr int TILE_BYTES  = 128 * 64;           // 8192 B
constexpr int STAGE_BYTES = 4 * TILE_BYTES;     // Ah, Al, Bh, Bl = 32768 B
constexpr int NSTAGE = 3;                       // 98304 B total -> 2 CTAs/SM

__device__ __forceinline__ uint32_t gswz(int row, int c) {
    return (uint32_t)(row * 64 + (((c + (row >> 1)) & 3) << 4));
}

__device__ __forceinline__ void ld_tile(uint32_t dst, const __nv_bfloat16* src, int ld, int tid) {
    #pragma unroll
    for (int j = 0; j < 2; j++) {
        int idx = tid + j * 256;        // 512 chunks: 128 rows x 4 x 16B
        int row = idx >> 2, c = idx & 3;
        uint32_t s = dst + gswz(row, c);
        const __nv_bfloat16* g = src + (size_t)row * ld + c * 8;
        asm volatile("cp.async.cg.shared.global [%0], [%1], 16;" :: "r"(s), "l"(g));
    }
}

__global__ void __launch_bounds__(256, 2)
gemm_bf16x3(const __nv_bfloat16* __restrict__ Ah, const __nv_bfloat16* __restrict__ Al,
            const __nv_bfloat16* __restrict__ Bh, const __nv_bfloat16* __restrict__ Bl,
            __nv_bfloat16* __restrict__ Ch, __nv_bfloat16* __restrict__ Cl,
            int K, int lda, int ldb, int ldc,
            long long aB, long long bB, long long cB, float alpha0, int thr)
{
    extern __shared__ __align__(1024) char dsm[];
    const uint32_t base = smem_u32(dsm);

    const int tid = threadIdx.x;
    const int lane = tid & 31, wid = tid >> 5;
    const int wm = wid & 1;
    const int wn = wid >> 1;
    const int m0 = blockIdx.x * BM, n0 = blockIdx.y * BN;
    const long long z = blockIdx.z;

    const __nv_bfloat16* pAh = Ah + z * aB + (size_t)m0 * lda;
    const __nv_bfloat16* pAl = Al + z * aB + (size_t)m0 * lda;
    const __nv_bfloat16* pBh = Bh + z * bB + (size_t)n0 * ldb;
    const __nv_bfloat16* pBl = Bl + z * bB + (size_t)n0 * ldb;

    const int a_row0 = wm * 64 + (lane & 15);                       // + mt*16
    const int a_csel = lane >> 4;                                    // + kk*2
    const int b_row0 = wn * 32 + ((lane >> 4) << 3) + (lane & 7);    // + nr*16
    const int b_csel = (lane >> 3) & 1;                              // + kk*2

    float acc[4][4][4] = {};

    const int nIter = K >> 5;
    #pragma unroll
    for (int s = 0; s < NSTAGE - 1; s++) {
        uint32_t sb = base + s * STAGE_BYTES;
        ld_tile(sb,                  pAh + s * BK, lda, tid);
        ld_tile(sb + TILE_BYTES,     pAl + s * BK, lda, tid);
        ld_tile(sb + 2 * TILE_BYTES, pBh + s * BK, ldb, tid);
        ld_tile(sb + 3 * TILE_BYTES, pBl + s * BK, ldb, tid);
        asm volatile("cp.async.commit_group;" ::: "memory");
    }

    for (int i = 0; i < nIter; i++) {
        asm volatile("cp.async.wait_group %0;" :: "n"(NSTAGE - 2) : "memory");
        __syncthreads();

        const int c = i + NSTAGE - 1;
        if (c < nIter) {
            uint32_t sb = base + (c % NSTAGE) * STAGE_BYTES;
            ld_tile(sb,                  pAh + c * BK, lda, tid);
            ld_tile(sb + TILE_BYTES,     pAl + c * BK, lda, tid);
            ld_tile(sb + 2 * TILE_BYTES, pBh + c * BK, ldb, tid);
            ld_tile(sb + 3 * TILE_BYTES, pBl + c * BK, ldb, tid);
        }
        asm volatile("cp.async.commit_group;" ::: "memory");   // uniform accounting

        const uint32_t sb   = base + (i % NSTAGE) * STAGE_BYTES;
        const uint32_t sA_h = sb;
        const uint32_t sA_l = sb + TILE_BYTES;
        const uint32_t sB_h = sb + 2 * TILE_BYTES;
        const uint32_t sB_l = sb + 3 * TILE_BYTES;

        #pragma unroll
        for (int kk = 0; kk < 2; kk++) {
            uint32_t fah[4][4], fal[4][4];
            #pragma unroll
            for (int mt = 0; mt < 4; mt++) {
                const uint32_t o = gswz(a_row0 + mt * 16, kk * 2 + a_csel);
                LDSM4(fah[mt], sA_h + o);
                LDSM4(fal[mt], sA_l + o);
            }
            #pragma unroll
            for (int nr = 0; nr < 2; nr++) {
                const uint32_t o = gswz(b_row0 + nr * 16, kk * 2 + b_csel);
                uint32_t fbh[4], fbl[4];
                LDSM4(fbh, sB_h + o);
                LDSM4(fbl, sB_l + o);
                #pragma unroll
                for (int mt = 0; mt < 4; mt++) {
                    MMA_BF16(acc[mt][nr * 2],     fah[mt], fbh[0], fbh[1]);
                    MMA_BF16(acc[mt][nr * 2],     fah[mt], fbl[0], fbl[1]);
                    MMA_BF16(acc[mt][nr * 2],     fal[mt], fbh[0], fbh[1]);
                    MMA_BF16(acc[mt][nr * 2 + 1], fah[mt], fbh[2], fbh[3]);
                    MMA_BF16(acc[mt][nr * 2 + 1], fah[mt], fbl[2], fbl[3]);
                    MMA_BF16(acc[mt][nr * 2 + 1], fal[mt], fbh[2], fbh[3]);
                }
            }
        }
    }

    // epilogue: scale (cols < thr) and write bf16 hi/lo pairs
    __nv_bfloat16* ch = Ch + z * cB;
    __nv_bfloat16* cl = Cl + z * cB;
    const int er = m0 + wm * 64 + (lane >> 2);
    const int ecb = n0 + wn * 32 + (lane & 3) * 2;
    #pragma unroll
    for (int mt = 0; mt < 4; mt++) {
        #pragma unroll
        for (int nt = 0; nt < 4; nt++) {
            const int col = ecb + nt * 8;
            const float a = (col < thr) ? alpha0 : 1.0f;
            const size_t o0 = (size_t)(er + mt * 16) * ldc + col;
            const size_t o1 = o0 + 8 * (size_t)ldc;
            uint32_t lo, hi;
            hi = pack_split(acc[mt][nt][0] * a, acc[mt][nt][1] * a, lo);
            *reinterpret_cast<uint32_t*>(ch + o0) = hi;
            *reinterpret_cast<uint32_t*>(cl + o0) = lo;
            hi = pack_split(acc[mt][nt][2] * a, acc[mt][nt][3] * a, lo);
            *reinterpret_cast<uint32_t*>(ch + o1) = hi;
            *reinterpret_cast<uint32_t*>(cl + o1) = lo;
        }
    }
}

// ================= fused flash attention =================
// grid (S/128, H), 256 thr. Q/K from g_qk{h,l} [h][s][256], V^T from g_vt{h,l} [h][e][t].
// smem: Qh Ql Kh Kl Vh Vl tiles, each 128x128 bf16, XOR-swizzled 256B rows.
constexpr int FT = 32768;                 // bytes per tile
#define FSWZ(row, c) ((uint32_t)((row) * 256 + (((c) ^ ((row) & 7)) << 4)))

__global__ void __launch_bounds__(256, 1)
flash_attn(const __nv_bfloat16* __restrict__ qk_h, const __nv_bfloat16* __restrict__ qk_l,
           const __nv_bfloat16* __restrict__ vt_h, const __nv_bfloat16* __restrict__ vt_l,
           float* __restrict__ out)
{
    extern __shared__ __align__(1024) char fsm[];
    const uint32_t sQh = smem_u32(fsm);
    const uint32_t sQl = sQh + FT, sKh = sQh + 2 * FT, sKl = sQh + 3 * FT;
    const uint32_t sVh = sQh + 4 * FT, sVl = sQh + 5 * FT;

    const int tid = threadIdx.x, lane = tid & 31, wr = tid >> 5;
    const int q0 = blockIdx.x * 128;
    const int h = blockIdx.y;
    const size_t qkB = (size_t)h * SEQ * 256;
    const size_t vB  = (size_t)h * E * SEQ;

    #define FLD(dst, src, ld)                                                             \
        do {                                                                              \
            _Pragma("unroll")                                                             \
            for (int j_ = 0; j_ < 8; j_++) {                                              \
                int idx_ = tid + j_ * 256;                                                \
                int row_ = idx_ >> 4, c_ = idx_ & 15;                                     \
                uint32_t d_ = (dst) + FSWZ(row_, c_);                                     \
                const __nv_bfloat16* g_ = (src) + (size_t)row_ * (ld) + c_ * 8;           \
                asm volatile("cp.async.cg.shared.global [%0], [%1], 16;" :: "r"(d_), "l"(g_)); \
            }                                                                             \
        } while (0)

    // warmup: Q + K0
    FLD(sQh, qk_h + qkB + (size_t)q0 * 256, 256);
    FLD(sQl, qk_l + qkB + (size_t)q0 * 256, 256);
    FLD(sKh, qk_h + qkB + 128, 256);
    FLD(sKl, qk_l + qkB + 128, 256);
    asm volatile("cp.async.commit_group;" ::: "memory");

    float o[16][4] = {};
    float m01 = -1e30f, m23 = -1e30f, l01 = 0.f, l23 = 0.f;
    const float LOG2E = 1.4426950408889634f;

    const int qrow = wr * 16 + (lane & 15);
    const int nrow = ((lane >> 4) << 3) + (lane & 7);

    for (int j = 0; j < 16; j++) {
        asm volatile("cp.async.wait_group 0;" ::: "memory");
        __syncthreads();    // K_j ready; all warps done with V_{j-1}

        // prefetch V_j
        FLD(sVh, vt_h + vB + j * 128, SEQ);
        FLD(sVl, vt_l + vB + j * 128, SEQ);
        asm volatile("cp.async.commit_group;" ::: "memory");

        // ---- S = Q * K_j^T  (bf16x3) ----
        float s[16][4] = {};
        #pragma unroll
        for (int ks = 0; ks < 8; ks++) {
            const int cA = ks * 2 + (lane >> 4);
            const uint32_t aoff = FSWZ(qrow, cA);
            uint32_t qh_f[4], ql_f[4];
            LDSM4(qh_f, sQh + aoff);
            LDSM4(ql_f, sQl + aoff);
            const int cB = ks * 2 + ((lane >> 3) & 1);
            #pragma unroll
            for (int np = 0; np < 8; np++) {
                const int br = np * 16 + nrow;
                const uint32_t boff = FSWZ(br, cB);
                uint32_t kh_f[4], kl_f[4];
                LDSM4(kh_f, sKh + boff);
                LDSM4(kl_f, sKl + boff);
                MMA_BF16(s[2 * np],     qh_f, kh_f[0], kh_f[1]);
                MMA_BF16(s[2 * np + 1], qh_f, kh_f[2], kh_f[3]);
                MMA_BF16(s[2 * np],     qh_f, kl_f[0], kl_f[1]);
                MMA_BF16(s[2 * np + 1], qh_f, kl_f[2], kl_f[3]);
                MMA_BF16(s[2 * np],     ql_f, kh_f[0], kh_f[1]);
                MMA_BF16(s[2 * np + 1], ql_f, kh_f[2], kh_f[3]);
            }
        }

        asm volatile("cp.async.wait_group 0;" ::: "memory");
        __syncthreads();    // V_j ready; all warps done reading K_j

        // prefetch K_{j+1}
        if (j + 1 < 16) {
            FLD(sKh, qk_h + qkB + (size_t)(j + 1) * 128 * 256 + 128, 256);
            FLD(sKl, qk_l + qkB + (size_t)(j + 1) * 128 * 256 + 128, 256);
        }
        asm volatile("cp.async.commit_group;" ::: "memory");

        // ---- online softmax ----
        float nm0 = m01, nm1 = m23;
        #pragma unroll
        for (int nt = 0; nt < 16; nt++) {
            nm0 = fmaxf(nm0, fmaxf(s[nt][0], s[nt][1]));
            nm1 = fmaxf(nm1, fmaxf(s[nt][2], s[nt][3]));
        }
        nm0 = fmaxf(nm0, __shfl_xor_sync(0xffffffffu, nm0, 1));
        nm0 = fmaxf(nm0, __shfl_xor_sync(0xffffffffu, nm0, 2));
        nm1 = fmaxf(nm1, __shfl_xor_sync(0xffffffffu, nm1, 1));
        nm1 = fmaxf(nm1, __shfl_xor_sync(0xffffffffu, nm1, 2));
        const float sc0 = fexp2((m01 - nm0) * LOG2E);
        const float sc1 = fexp2((m23 - nm1) * LOG2E);
        m01 = nm0; m23 = nm1;
        float rs0 = 0.f, rs1 = 0.f;
        #pragma unroll
        for (int nt = 0; nt < 16; nt++) {
            s[nt][0] = fexp2((s[nt][0] - m01) * LOG2E);
            s[nt][1] = fexp2((s[nt][1] - m01) * LOG2E);
            s[nt][2] = fexp2((s[nt][2] - m23) * LOG2E);
            s[nt][3] = fexp2((s[nt][3] - m23) * LOG2E);
            rs0 += s[nt][0] + s[nt][1];
            rs1 += s[nt][2] + s[nt][3];
        }
        rs0 += __shfl_xor_sync(0xffffffffu, rs0, 1);
        rs0 += __shfl_xor_sync(0xffffffffu, rs0, 2);
        rs1 += __shfl_xor_sync(0xffffffffu, rs1, 1);
        rs1 += __shfl_xor_sync(0xffffffffu, rs1, 2);
        l01 = l01 * sc0 + rs0;
        l23 = l23 * sc1 + rs1;
        #pragma unroll
        for (int nt = 0; nt < 16; nt++) {
            o[nt][0] *= sc0; o[nt][1] *= sc0;
            o[nt][2] *= sc1; o[nt][3] *= sc1;
        }

        // ---- O += P * V  (bf16x3) ----
        #pragma unroll
        for (int ks = 0; ks < 8; ks++) {
            uint32_t ah_f[4], al_f[4];
            ah_f[0] = pack_split(s[2 * ks][0],     s[2 * ks][1],     al_f[0]);
            ah_f[1] = pack_split(s[2 * ks][2],     s[2 * ks][3],     al_f[1]);
            ah_f[2] = pack_split(s[2 * ks + 1][0], s[2 * ks + 1][1], al_f[2]);
            ah_f[3] = pack_split(s[2 * ks + 1][2], s[2 * ks + 1][3], al_f[3]);
            const int cV = ks * 2 + ((lane >> 3) & 1);
            #pragma unroll
            for (int ep = 0; ep < 8; ep++) {
                const int vr = ep * 16 + nrow;
                const uint32_t voff = FSWZ(vr, cV);
                uint32_t vh_f[4], vl_f[4];
                LDSM4(vh_f, sVh + voff);
                LDSM4(vl_f, sVl + voff);
                MMA_BF16(o[2 * ep],     ah_f, vh_f[0], vh_f[1]);
                MMA_BF16(o[2 * ep + 1], ah_f, vh_f[2], vh_f[3]);
                MMA_BF16(o[2 * ep],     ah_f, vl_f[0], vl_f[1]);
                MMA_BF16(o[2 * ep + 1], ah_f, vl_f[2], vl_f[3]);
                MMA_BF16(o[2 * ep],     al_f, vh_f[0], vh_f[1]);
                MMA_BF16(o[2 * ep + 1], al_f, vh_f[2], vh_f[3]);
            }
        }
    }

    // epilogue
    const float inv0 = 1.0f / l01, inv1 = 1.0f / l23;
    const int row = q0 + wr * 16 + (lane >> 2);
    float* po = out + (size_t)row * DM + h * 128 + (lane & 3) * 2;
    #pragma unroll
    for (int nt = 0; nt < 16; nt++) {
        float2 v0 = { o[nt][0] * inv0, o[nt][1] * inv0 };
        float2 v1 = { o[nt][2] * inv1, o[nt][3] * inv1 };
        *reinterpret_cast<float2*>(po + nt * 8) = v0;
        *reinterpret_cast<float2*>(po + 8 * DM + nt * 8) = v1;
    }
}

// ----------------- fp32 -> bf16 hi/lo split (x) -----------------
__global__ void split_f32(const float* __restrict__ s,
                          __nv_bfloat16* __restrict__ hi, __nv_bfloat16* __restrict__ lo,
                          size_t nelem)
{
    size_t i = (size_t)blockIdx.x * blockDim.x + threadIdx.x;
    size_t stride = (size_t)gridDim.x * blockDim.x;
    for (size_t p = i * 4; p < nelem; p += stride * 4) {
        float4 v = *reinterpret_cast<const float4*>(s + p);
        uint32_t l0, l1;
        uint32_t h0 = pack_split(v.x, v.y, l0);
        uint32_t h1 = pack_split(v.z, v.w, l1);
        *reinterpret_cast<uint32_t*>(hi + p)     = h0;
        *reinterpret_cast<uint32_t*>(hi + p + 2) = h1;
        *reinterpret_cast<uint32_t*>(lo + p)     = l0;
        *reinterpret_cast<uint32_t*>(lo + p + 2) = l1;
    }
}

// ----------------- transpose + split: dst[c][r] = src[r][c] -----------------
__global__ void trans_split(const float* __restrict__ src,
                            __nv_bfloat16* __restrict__ th, __nv_bfloat16* __restrict__ tl,
                            int srows, int scols, long long sBatch, long long dBatch, int soff)
{
    __shared__ float t[32][33];
    const float* s = src + (size_t)blockIdx.z * sBatch + soff;
    int r0 = blockIdx.x * 32, c0 = blockIdx.y * 32;
    int tx = threadIdx.x, ty = threadIdx.y;
    #pragma unroll
    for (int j = 0; j < 32; j += 8)
        t[ty + j][tx] = s[(size_t)(r0 + ty + j) * scols + c0 + tx];
    __syncthreads();
    size_t db = (size_t)blockIdx.z * dBatch;
    #pragma unroll
    for (int j = 0; j < 32; j += 8) {
        float v = t[tx][ty + j];
        __nv_bfloat16 hv = __float2bfloat16(v);
        size_t o = db + (size_t)(c0 + ty + j) * srows + r0 + tx;
        th[o] = hv;
        tl[o] = __float2bfloat16(v - __bfloat162float(hv));
    }
}

// ----------------- launch -----------------
extern "C" void kernel_launch(void* const* d_in, const int* in_sizes, int n_in,
                              void* d_out, int out_size)
{
    const float* x = (const float*)d_in[0];   // [S, D]
    const float* w = (const float*)d_in[1];   // [H, D, 3E]
    float* out = (float*)d_out;               // [S, H*E]

    __nv_bfloat16 *xh, *xl, *wth, *wtl, *qkh, *qkl, *vth, *vtl;
    cudaGetSymbolAddress((void**)&xh, g_xh);
    cudaGetSymbolAddress((void**)&xl, g_xl);
    cudaGetSymbolAddress((void**)&wth, g_wth);
    cudaGetSymbolAddress((void**)&wtl, g_wtl);
    cudaGetSymbolAddress((void**)&qkh, g_qkh);
    cudaGetSymbolAddress((void**)&qkl, g_qkl);
    cudaGetSymbolAddress((void**)&vth, g_vth);
    cudaGetSymbolAddress((void**)&vtl, g_vtl);

    const int smemG = NSTAGE * STAGE_BYTES;   // 98304
    cudaFuncSetAttribute(gemm_bf16x3, cudaFuncAttributeMaxDynamicSharedMemorySize, smemG);
    const int smemF = 6 * FT;                 // 196608
    cudaFuncSetAttribute(flash_attn, cudaFuncAttributeMaxDynamicSharedMemorySize, smemF);

    const float inv_sqrt_e = 0.08838834764831845f;  // 1/sqrt(128)

    // prepass
    split_f32<<<2048, 256>>>(x, xh, xl, (size_t)SEQ * DM);
    trans_split<<<dim3(DM / 32, NE3 / 32, H), dim3(32, 8)>>>(
        w, wth, wtl, DM, NE3, (long long)DM * NE3, (long long)NE3 * DM, 0);

    // 1a) QK: qk[h][s][0:256] = x @ w[h][:, 0:256], Q cols pre-scaled by 1/sqrt(E)
    gemm_bf16x3<<<dim3(SEQ / BM, 256 / BN, H), 256, smemG>>>(
        xh, xl, wth, wtl, qkh, qkl,
        DM, DM, DM, 256,
        0LL, (long long)NE3 * DM, (long long)SEQ * 256, inv_sqrt_e, 128);

    // 1b) V^T: vt[h][e][t] = Wv^T @ x^T  (A = wt rows 256..383, B = x)
    gemm_bf16x3<<<dim3(E / BM, SEQ / BN, H), 256, smemG>>>(
        wth + (size_t)256 * DM, wtl + (size_t)256 * DM, xh, xl, vth, vtl,
        DM, DM, DM, SEQ,
        (long long)NE3 * DM, 0LL, (long long)E * SEQ, 1.0f, 0);

    // 2) fused attention
    flash_attn<<<dim3(SEQ / 128, H), 256, smemF>>>(qkh, qkl, vth, vtl, out);
}